// round 2
// baseline (speedup 1.0000x reference)
#include <cuda_runtime.h>
#include <cuda_bf16.h>
#include <cstdint>

#define KTAGS 256
#define NTHREADS 256

// exp(transitions) as bf16, precomputed once per launch (128 KB static global).
__device__ __nv_bfloat16 d_ET[KTAGS * KTAGS];

__global__ void crf_prep_kernel(const float* __restrict__ trans) {
    int idx = blockIdx.x * blockDim.x + threadIdx.x;
    if (idx < KTAGS * KTAGS) {
        d_ET[idx] = __float2bfloat16(expf(trans[idx]));
    }
}

__device__ __forceinline__ float blo(unsigned int w) { return __uint_as_float(w << 16); }
__device__ __forceinline__ float bhi(unsigned int w) { return __uint_as_float(w & 0xffff0000u); }

// SMEM layout (dynamic):
//   [0, 131072)            ET as bf16 (stored as uint words, 2 bf16 per word)
//   [131072, 132096)       p[256] floats
//   [132096, 140288)       partials[8][256] floats
//   [140288, 140352)       red[16] floats (red[8] holds the numerator)
#define SMEM_ET    0
#define SMEM_P     131072
#define SMEM_PART  132096
#define SMEM_RED   140288
#define SMEM_TOTAL 140352

__global__ __launch_bounds__(NTHREADS, 1)
void crf_main_kernel(const float* __restrict__ emissions,
                     const int* __restrict__ targets,
                     const int* __restrict__ masks,
                     const float* __restrict__ start_t,
                     const float* __restrict__ end_t,
                     const float* __restrict__ trans,
                     float* __restrict__ out,
                     int S)
{
    extern __shared__ char smem[];
    unsigned int* ets = (unsigned int*)(smem + SMEM_ET);   // [256][128] uint (2 bf16 each)
    float* p_s = (float*)(smem + SMEM_P);
    float* ps  = (float*)(smem + SMEM_PART);
    float* red = (float*)(smem + SMEM_RED);

    const int tid  = threadIdx.x;
    const int b    = blockIdx.x;
    const int lane = tid & 31;
    const int wid  = tid >> 5;

    const float* emb      = emissions + (size_t)b * S * KTAGS;
    const int* tg         = targets + (size_t)b * S;
    const int* mrow       = masks + (size_t)b * S;      // int32 mask elements

    // ---- Load ET into shared memory (128 KB, coalesced uint4) ----
    {
        const uint4* src = (const uint4*)d_ET;   // 8192 uint4
        uint4* dst = (uint4*)ets;
        #pragma unroll 4
        for (int i = tid; i < 8192; i += NTHREADS) dst[i] = src[i];
    }

    // ---- Numerator (gather path), partial per thread ----
    float npart = 0.f;
    int cnt = 0;
    for (int t = tid; t < S; t += NTHREADS) {
        int m = mrow[t] != 0;
        cnt += m;
        if (t >= 1 && m) {
            int pv = tg[t - 1], cu = tg[t];
            npart += trans[pv * KTAGS + cu] + emb[(size_t)t * KTAGS + cu];
        }
    }
    __syncthreads();              // ET load done; ps/p_s free for reduction scratch
    ps[tid]  = npart;
    p_s[tid] = (float)cnt;
    __syncthreads();
    if (tid == 0) {
        float tot = 0.f, c = 0.f;
        for (int i = 0; i < NTHREADS; i++) { tot += ps[i]; c += p_s[i]; }
        int seq_end = (int)c - 1;
        int t0 = tg[0];
        tot += start_t[t0] + emb[t0] + end_t[tg[seq_end]];
        red[8] = tot;             // stash numerator; loop only uses red[0..7]
    }

    // ---- Forward recursion ----
    float score = start_t[tid] + emb[tid];           // t = 0
    const unsigned int* etbase = ets + (wid * 32) * 128 + lane * 4;
    const float* p_base = p_s + wid * 32;
    float* prt = ps + wid * KTAGS + lane * 8;

    for (int t = 1; t < S; t++) {
        // (1) global max of score via warp shuffle + cross-warp smem
        float m = score;
        #pragma unroll
        for (int o = 16; o > 0; o >>= 1)
            m = fmaxf(m, __shfl_xor_sync(0xffffffffu, m, o));
        if (lane == 0) red[wid] = m;
        __syncthreads();
        float M = red[0];
        #pragma unroll
        for (int w = 1; w < 8; w++) M = fmaxf(M, red[w]);

        // (2) p = exp(score - M); prefetch emission + mask for this step
        p_s[tid] = __expf(score - M);
        float e  = emb[(size_t)t * KTAGS + tid];
        int  msk = mrow[t];
        __syncthreads();

        // (3) matvec: warp wid covers i in [32*wid, 32*wid+32), lane covers 8 cols
        float a0 = 0.f, a1 = 0.f, a2 = 0.f, a3 = 0.f;
        float a4 = 0.f, a5 = 0.f, a6 = 0.f, a7 = 0.f;
        #pragma unroll
        for (int ii = 0; ii < 32; ii++) {
            float pi = p_base[ii];
            uint4 w4 = *(const uint4*)(etbase + ii * 128);
            a0 = fmaf(pi, blo(w4.x), a0);
            a1 = fmaf(pi, bhi(w4.x), a1);
            a2 = fmaf(pi, blo(w4.y), a2);
            a3 = fmaf(pi, bhi(w4.y), a3);
            a4 = fmaf(pi, blo(w4.z), a4);
            a5 = fmaf(pi, bhi(w4.z), a5);
            a6 = fmaf(pi, blo(w4.w), a6);
            a7 = fmaf(pi, bhi(w4.w), a7);
        }
        ((float4*)prt)[0] = make_float4(a0, a1, a2, a3);
        ((float4*)prt)[1] = make_float4(a4, a5, a6, a7);
        __syncthreads();

        // (4) reduce 8 partials for my column, update score
        float ssum = 0.f;
        #pragma unroll
        for (int g = 0; g < 8; g++) ssum += ps[g * KTAGS + tid];
        float nxt = M + __logf(ssum) + e;
        score = msk ? nxt : score;
        __syncthreads();          // protect red/p_s/ps reuse next iteration
    }

    // ---- Final: denominator = logsumexp(score + end), out = num - denom ----
    float v = score + end_t[tid];
    float m2 = v;
    #pragma unroll
    for (int o = 16; o > 0; o >>= 1)
        m2 = fmaxf(m2, __shfl_xor_sync(0xffffffffu, m2, o));
    if (lane == 0) red[wid] = m2;
    __syncthreads();
    float M2 = red[0];
    #pragma unroll
    for (int w = 1; w < 8; w++) M2 = fmaxf(M2, red[w]);

    float pe = __expf(v - M2);
    #pragma unroll
    for (int o = 16; o > 0; o >>= 1)
        pe += __shfl_xor_sync(0xffffffffu, pe, o);
    __syncthreads();              // red[0..7] reads above done before rewrite
    if (lane == 0) red[wid] = pe;
    __syncthreads();
    if (tid == 0) {
        float s = 0.f;
        #pragma unroll
        for (int w = 0; w < 8; w++) s += red[w];
        out[b] = red[8] - (M2 + __logf(s));
    }
}

extern "C" void kernel_launch(void* const* d_in, const int* in_sizes, int n_in,
                              void* d_out, int out_size) {
    const float* emissions = (const float*)d_in[0];
    const int*   targets   = (const int*)d_in[1];
    const int*   masks     = (const int*)d_in[2];
    const float* start_t   = (const float*)d_in[3];
    const float* end_t     = (const float*)d_in[4];
    const float* trans     = (const float*)d_in[5];
    float*       out       = (float*)d_out;

    int B = out_size;                 // one output per batch element
    int S = in_sizes[1] / B;          // targets is (B, S)

    // Precompute exp(transitions) in bf16
    crf_prep_kernel<<<(KTAGS * KTAGS + 255) / 256, 256>>>(trans);

    static bool attr_set = false;
    if (!attr_set) {
        cudaFuncSetAttribute(crf_main_kernel,
                             cudaFuncAttributeMaxDynamicSharedMemorySize,
                             SMEM_TOTAL);
        attr_set = true;
    }

    crf_main_kernel<<<B, NTHREADS, SMEM_TOTAL>>>(
        emissions, targets, masks, start_t, end_t, trans, out, S);
}

// round 3
// speedup vs baseline: 1.9791x; 1.9791x over previous
#include <cuda_runtime.h>
#include <cuda_fp16.h>
#include <cstdint>

#define KTAGS 256
#define NTH   256
#define SMAX  1024

// exp(transitions) as fp16, precomputed once per launch (128 KB static global).
__device__ __half d_ETh[KTAGS * KTAGS];

__global__ void crf_prep(const float* __restrict__ trans) {
    int i = blockIdx.x * blockDim.x + threadIdx.x;
    if (i < KTAGS * KTAGS) d_ETh[i] = __float2half(expf(trans[i]));
}

__device__ __forceinline__ __half2 u2h(unsigned int u) {
    __half2 h; *(unsigned int*)&h = u; return h;
}
__device__ __forceinline__ unsigned int h2u(__half2 h) {
    return *(unsigned int*)&h;
}

__global__ __launch_bounds__(NTH, 1)
void crf_main(const float* __restrict__ emissions,
              const int* __restrict__ targets,
              const int* __restrict__ masks,
              const float* __restrict__ start_t,
              const float* __restrict__ end_t,
              const float* __restrict__ trans,
              float* __restrict__ out,
              int S)
{
    __shared__ uint4 part[2][8][32];      // [parity][group(warp)][lane] : 8 half2 partials
    __shared__ float red[2][8];           // cross-warp max scratch (double-buffered)
    __shared__ float rscr[NTH], cscr[NTH];
    __shared__ float num_smem;
    __shared__ int   ms[SMAX];

    const int tid  = threadIdx.x;
    const int b    = blockIdx.x;
    const int lane = tid & 31;
    const int wid  = tid >> 5;

    const float* emb  = emissions + (size_t)b * S * KTAGS;
    const int*   tg   = targets  + (size_t)b * S;
    const int*   mrow = masks    + (size_t)b * S;

    // ---- ET slice into registers: rows [32*wid, 32*wid+32), cols [8*lane, 8*lane+8) ----
    unsigned int et[32][4];
    {
        const uint4* etg = (const uint4*)d_ETh;   // 32 uint4 per row
        #pragma unroll
        for (int ii = 0; ii < 32; ii++) {
            uint4 v = etg[(size_t)(wid * 32 + ii) * 32 + lane];
            et[ii][0] = v.x; et[ii][1] = v.y; et[ii][2] = v.z; et[ii][3] = v.w;
        }
    }

    // ---- masks into SMEM ----
    for (int t = tid; t < S && t < SMAX; t += NTH) ms[t] = mrow[t];

    // ---- Numerator (gather), partial per thread ----
    float npart = 0.f;
    int cnt = 0;
    for (int t = tid; t < S; t += NTH) {
        int m = mrow[t] != 0;
        cnt += m;
        if (t >= 1 && m) {
            int pv = tg[t - 1], cu = tg[t];
            npart += trans[pv * KTAGS + cu] + emb[(size_t)t * KTAGS + cu];
        }
    }
    rscr[tid] = npart;
    cscr[tid] = (float)cnt;
    __syncthreads();
    if (tid == 0) {
        float tot = 0.f, c = 0.f;
        for (int i = 0; i < NTH; i++) { tot += rscr[i]; c += cscr[i]; }
        int seq_end = (int)c - 1;
        int t0 = tg[0];
        num_smem = tot + start_t[t0] + emb[t0] + end_t[tg[seq_end]];
    }
    __syncthreads();

    // ---- Forward recursion ----
    float score = start_t[tid] + emb[tid];               // t = 0
    float e_cur = emb[(size_t)KTAGS + tid];              // emission for t = 1
    unsigned int* partU = (unsigned int*)part;

    for (int t = 1; t < S; t++) {
        const int par = t & 1;

        // prefetch next emission (hide DRAM latency across the step)
        int tn = (t + 1 < S) ? (t + 1) : (S - 1);
        float e_nxt = emb[(size_t)tn * KTAGS + tid];
        int   msk   = ms[t];

        // (1) global max of score
        float m = score;
        #pragma unroll
        for (int o = 16; o > 0; o >>= 1)
            m = fmaxf(m, __shfl_xor_sync(0xffffffffu, m, o));
        if (lane == 0) red[par][wid] = m;
        __syncthreads();                                  // A
        float M = red[par][0];
        #pragma unroll
        for (int w = 1; w < 8; w++) M = fmaxf(M, red[par][w]);

        // (2) p = exp(score - M), packed dup into half2
        float pf = __expf(score - M);
        unsigned int p2u = h2u(__float2half2_rn(pf));

        // (3) matvec slice: rows from this warp's own lanes via shuffle
        __half2 a0 = u2h(0u), a1 = u2h(0u), a2 = u2h(0u), a3 = u2h(0u);
        #pragma unroll
        for (int ii = 0; ii < 32; ii++) {
            __half2 q = u2h(__shfl_sync(0xffffffffu, p2u, ii));
            a0 = __hfma2(u2h(et[ii][0]), q, a0);
            a1 = __hfma2(u2h(et[ii][1]), q, a1);
            a2 = __hfma2(u2h(et[ii][2]), q, a2);
            a3 = __hfma2(u2h(et[ii][3]), q, a3);
        }
        part[par][wid][lane] = make_uint4(h2u(a0), h2u(a1), h2u(a2), h2u(a3));
        __syncthreads();                                  // B

        // (4) sum 8 group partials for my column (tid), in half2 then extract
        __half2 s2 = u2h(0u);
        const int ubase = par * 8 * 128 + (tid >> 1);
        #pragma unroll
        for (int g = 0; g < 8; g++)
            s2 = __hadd2(s2, u2h(partU[ubase + g * 128]));
        float ssum = (tid & 1) ? __high2float(s2) : __low2float(s2);

        float nxt = M + __logf(ssum) + e_cur;
        score = msk ? nxt : score;
        e_cur = e_nxt;
    }

    // ---- Final: denominator = logsumexp(score + end) ----
    float v = score + end_t[tid];
    float m2 = v;
    #pragma unroll
    for (int o = 16; o > 0; o >>= 1)
        m2 = fmaxf(m2, __shfl_xor_sync(0xffffffffu, m2, o));
    if (lane == 0) red[0][wid] = m2;
    __syncthreads();
    float M2 = red[0][0];
    #pragma unroll
    for (int w = 1; w < 8; w++) M2 = fmaxf(M2, red[0][w]);

    float pe = __expf(v - M2);
    #pragma unroll
    for (int o = 16; o > 0; o >>= 1)
        pe += __shfl_xor_sync(0xffffffffu, pe, o);
    if (lane == 0) red[1][wid] = pe;
    __syncthreads();
    if (tid == 0) {
        float s = 0.f;
        #pragma unroll
        for (int w = 0; w < 8; w++) s += red[1][w];
        out[b] = num_smem - (M2 + __logf(s));
    }
}

extern "C" void kernel_launch(void* const* d_in, const int* in_sizes, int n_in,
                              void* d_out, int out_size) {
    const float* emissions = (const float*)d_in[0];
    const int*   targets   = (const int*)d_in[1];
    const int*   masks     = (const int*)d_in[2];
    const float* start_t   = (const float*)d_in[3];
    const float* end_t     = (const float*)d_in[4];
    const float* trans     = (const float*)d_in[5];
    float*       out       = (float*)d_out;

    int B = out_size;
    int S = in_sizes[1] / B;

    crf_prep<<<(KTAGS * KTAGS + 255) / 256, 256>>>(trans);
    crf_main<<<B, NTH>>>(emissions, targets, masks, start_t, end_t, trans, out, S);
}

// round 5
// speedup vs baseline: 2.1706x; 1.0967x over previous
#include <cuda_runtime.h>
#include <cuda_fp16.h>
#include <cstdint>

#define KTAGS 256
#define NTH   256
#define SMAX  1024
#define LN2F  0.69314718055994531f

// exp(transitions) as fp16 (128 KB static global).
__device__ __half d_ETh[KTAGS * KTAGS];

__global__ void crf_prep(const float* __restrict__ trans) {
    int i = blockIdx.x * blockDim.x + threadIdx.x;
    if (i < KTAGS * KTAGS) d_ETh[i] = __float2half(expf(trans[i]));
}

__device__ __forceinline__ __half2 u2h(unsigned int u) { __half2 h; *(unsigned int*)&h = u; return h; }
__device__ __forceinline__ unsigned int h2u(__half2 h) { return *(unsigned int*)&h; }

__global__ __launch_bounds__(NTH, 1)
void crf_main(const float* __restrict__ emissions,
              const int* __restrict__ targets,
              const int* __restrict__ masks,
              const float* __restrict__ start_t,
              const float* __restrict__ end_t,
              const float* __restrict__ trans,
              float* __restrict__ out,
              int S)
{
    __shared__ uint4 part[2][8][32];                 // double-buffered matvec partials
    __shared__ __align__(16) float ws[2][8];         // double-buffered warp sums of p (POST-scale)
    __shared__ unsigned int pvec[NTH];               // p as dup-half2
    __shared__ float red[8];
    __shared__ float rscr[NTH], cscr[NTH];
    __shared__ float num_smem;
    __shared__ int ms[SMAX];

    const int tid = threadIdx.x, b = blockIdx.x, lane = tid & 31, wid = tid >> 5;
    const float* emb  = emissions + (size_t)b * S * KTAGS;
    const int*   tg   = targets  + (size_t)b * S;
    const int*   mrow = masks    + (size_t)b * S;

    // ---- ET slice into registers: rows [32*wid,32*wid+32), cols [8*lane,8*lane+8) ----
    unsigned int et[32][4];
    {
        const uint4* etg = (const uint4*)d_ETh;
        #pragma unroll
        for (int ii = 0; ii < 32; ii++) {
            uint4 v = etg[(size_t)(wid * 32 + ii) * 32 + lane];
            et[ii][0] = v.x; et[ii][1] = v.y; et[ii][2] = v.z; et[ii][3] = v.w;
        }
    }

    // ---- masks into SMEM ----
    for (int t = tid; t < S && t < SMAX; t += NTH) ms[t] = mrow[t];

    // ---- Numerator ----
    float npart = 0.f; int cnt = 0;
    for (int t = tid; t < S; t += NTH) {
        int m = mrow[t] != 0; cnt += m;
        if (t >= 1 && m) {
            int pv = tg[t - 1], cu = tg[t];
            npart += trans[pv * KTAGS + cu] + emb[(size_t)t * KTAGS + cu];
        }
    }
    rscr[tid] = npart; cscr[tid] = (float)cnt;
    __syncthreads();
    if (tid == 0) {
        float tot = 0.f, c = 0.f;
        for (int i = 0; i < NTH; i++) { tot += rscr[i]; c += cscr[i]; }
        int seq_end = (int)c - 1; int t0 = tg[0];
        num_smem = tot + start_t[t0] + emb[t0] + end_t[tg[seq_end]];
    }

    // ---- Init (t = 0): exact max-normalization once ----
    float s0 = start_t[tid] + emb[tid];
    float m = s0;
    #pragma unroll
    for (int o = 16; o > 0; o >>= 1) m = fmaxf(m, __shfl_xor_sync(0xffffffffu, m, o));
    if (lane == 0) red[wid] = m;
    __syncthreads();
    float M = red[0];
    #pragma unroll
    for (int w = 1; w < 8; w++) M = fmaxf(M, red[w]);
    float myp = __expf(s0 - M);
    int   ktot = 0;                       // exact power-of-2 bookkeeping (int)

    pvec[tid] = h2u(__float2half2_rn(myp));
    float qs = myp;                       // warp sums of POST-scale p
    #pragma unroll
    for (int o = 16; o > 0; o >>= 1) qs += __shfl_xor_sync(0xffffffffu, qs, o);
    if (lane == 0) ws[0][wid] = qs;
    __syncwarp();

    // ---- matvec for step 0 into part[0] ----
    {
        __half2 a0 = u2h(0u), a1 = u2h(0u), a2 = u2h(0u), a3 = u2h(0u);
        const uint4* pv4 = ((const uint4*)pvec) + wid * 8;
        #pragma unroll
        for (int k = 0; k < 8; k++) {
            uint4 v = pv4[k];
            a0 = __hfma2(u2h(et[4*k+0][0]), u2h(v.x), a0);
            a1 = __hfma2(u2h(et[4*k+0][1]), u2h(v.x), a1);
            a2 = __hfma2(u2h(et[4*k+0][2]), u2h(v.x), a2);
            a3 = __hfma2(u2h(et[4*k+0][3]), u2h(v.x), a3);
            a0 = __hfma2(u2h(et[4*k+1][0]), u2h(v.y), a0);
            a1 = __hfma2(u2h(et[4*k+1][1]), u2h(v.y), a1);
            a2 = __hfma2(u2h(et[4*k+1][2]), u2h(v.y), a2);
            a3 = __hfma2(u2h(et[4*k+1][3]), u2h(v.y), a3);
            a0 = __hfma2(u2h(et[4*k+2][0]), u2h(v.z), a0);
            a1 = __hfma2(u2h(et[4*k+2][1]), u2h(v.z), a1);
            a2 = __hfma2(u2h(et[4*k+2][2]), u2h(v.z), a2);
            a3 = __hfma2(u2h(et[4*k+2][3]), u2h(v.z), a3);
            a0 = __hfma2(u2h(et[4*k+3][0]), u2h(v.w), a0);
            a1 = __hfma2(u2h(et[4*k+3][1]), u2h(v.w), a1);
            a2 = __hfma2(u2h(et[4*k+3][2]), u2h(v.w), a2);
            a3 = __hfma2(u2h(et[4*k+3][3]), u2h(v.w), a3);
        }
        part[0][wid][lane] = make_uint4(h2u(a0), h2u(a1), h2u(a2), h2u(a3));
    }

    // emission pipeline: ee_cur = exp(emission) for t=1, raw for t=2
    float ee_cur    = __expf(emb[(size_t)((1 < S) ? 1 : 0) * KTAGS + tid]);
    float eraw_next = emb[(size_t)((2 < S) ? 2 : (S - 1)) * KTAGS + tid];

    const unsigned int* partU = (const unsigned int*)part;

    // ---- Forward recursion: one barrier per step ----
    for (int t = 1; t < S; t++) {
        const int par = t & 1, pre = par ^ 1;
        __syncthreads();

        int tn = (t + 2 < S) ? (t + 2) : (S - 1);
        float eraw2 = emb[(size_t)tn * KTAGS + tid];
        int msk = (t < SMAX) ? ms[t] : mrow[t];

        // ssum from 8 group partials (half2 tree, then extract my half)
        const unsigned int* pb = partU + pre * 1024 + (tid >> 1);
        __half2 x0 = u2h(pb[0]);
        __half2 x1 = u2h(pb[128]);
        __half2 x2 = u2h(pb[256]);
        __half2 x3 = u2h(pb[384]);
        __half2 x4 = u2h(pb[512]);
        __half2 x5 = u2h(pb[640]);
        __half2 x6 = u2h(pb[768]);
        __half2 x7 = u2h(pb[896]);
        __half2 sv = __hadd2(__hadd2(__hadd2(x0, x1), __hadd2(x2, x3)),
                             __hadd2(__hadd2(x4, x5), __hadd2(x6, x7)));
        float ssum = (tid & 1) ? __high2float(sv) : __low2float(sv);

        // lag-1 normalizer from previous step's POST-scale p-sum: stable forever.
        // ke = ilogb(Sp_prev) + 8  (2^8 ~ growth of Sigma q per step for K=256)
        float4 w0 = *(const float4*)&ws[pre][0];
        float4 w1 = *(const float4*)&ws[pre][4];
        float Sp = ((w0.x + w0.y) + (w0.z + w0.w)) + ((w1.x + w1.y) + (w1.z + w1.w));
        unsigned int sb = __float_as_uint(Sp);
        int ke = (int)(sb >> 23) - 119;                                   // ilogb+8
        float sf = __uint_as_float((unsigned int)(246 - (int)(sb >> 23)) << 23);  // 2^-ke

        float q = ssum * ee_cur;
        if (msk) { myp = q * sf; ktot += ke; }

        pvec[tid] = h2u(__float2half2_rn(myp));
        float psum = myp;                 // POST-scale sum
        #pragma unroll
        for (int o = 16; o > 0; o >>= 1) psum += __shfl_xor_sync(0xffffffffu, psum, o);
        if (lane == 0) ws[par][wid] = psum;
        __syncwarp();

        // matvec over new p
        __half2 a0 = u2h(0u), a1 = u2h(0u), a2 = u2h(0u), a3 = u2h(0u);
        const uint4* pv4 = ((const uint4*)pvec) + wid * 8;
        #pragma unroll
        for (int k = 0; k < 8; k++) {
            uint4 v = pv4[k];
            a0 = __hfma2(u2h(et[4*k+0][0]), u2h(v.x), a0);
            a1 = __hfma2(u2h(et[4*k+0][1]), u2h(v.x), a1);
            a2 = __hfma2(u2h(et[4*k+0][2]), u2h(v.x), a2);
            a3 = __hfma2(u2h(et[4*k+0][3]), u2h(v.x), a3);
            a0 = __hfma2(u2h(et[4*k+1][0]), u2h(v.y), a0);
            a1 = __hfma2(u2h(et[4*k+1][1]), u2h(v.y), a1);
            a2 = __hfma2(u2h(et[4*k+1][2]), u2h(v.y), a2);
            a3 = __hfma2(u2h(et[4*k+1][3]), u2h(v.y), a3);
            a0 = __hfma2(u2h(et[4*k+2][0]), u2h(v.z), a0);
            a1 = __hfma2(u2h(et[4*k+2][1]), u2h(v.z), a1);
            a2 = __hfma2(u2h(et[4*k+2][2]), u2h(v.z), a2);
            a3 = __hfma2(u2h(et[4*k+2][3]), u2h(v.z), a3);
            a0 = __hfma2(u2h(et[4*k+3][0]), u2h(v.w), a0);
            a1 = __hfma2(u2h(et[4*k+3][1]), u2h(v.w), a1);
            a2 = __hfma2(u2h(et[4*k+3][2]), u2h(v.w), a2);
            a3 = __hfma2(u2h(et[4*k+3][3]), u2h(v.w), a3);
        }
        part[par][wid][lane] = make_uint4(h2u(a0), h2u(a1), h2u(a2), h2u(a3));

        // promote emission pipeline (exp off the critical path)
        ee_cur    = __expf(eraw_next);
        eraw_next = eraw2;
    }

    // ---- Final: denominator = M + ktot*ln2 + log(Sigma myp * exp(end)) ----
    float v = myp * __expf(end_t[tid]);
    float sv = v;
    #pragma unroll
    for (int o = 16; o > 0; o >>= 1) sv += __shfl_xor_sync(0xffffffffu, sv, o);
    if (lane == 0) red[wid] = sv;
    __syncthreads();
    if (tid == 0) {
        float tot = 0.f;
        #pragma unroll
        for (int w = 0; w < 8; w++) tot += red[w];
        out[b] = num_smem - (M + (float)ktot * LN2F + __logf(tot));
    }
}

extern "C" void kernel_launch(void* const* d_in, const int* in_sizes, int n_in,
                              void* d_out, int out_size) {
    const float* emissions = (const float*)d_in[0];
    const int*   targets   = (const int*)d_in[1];
    const int*   masks     = (const int*)d_in[2];
    const float* start_t   = (const float*)d_in[3];
    const float* end_t     = (const float*)d_in[4];
    const float* trans     = (const float*)d_in[5];
    float*       out       = (float*)d_out;

    int B = out_size;
    int S = in_sizes[1] / B;

    crf_prep<<<(KTAGS * KTAGS + 255) / 256, 256>>>(trans);
    crf_main<<<B, NTH>>>(emissions, targets, masks, start_t, end_t, trans, out, S);
}